// round 7
// baseline (speedup 1.0000x reference)
#include <cuda_runtime.h>
#include <math_constants.h>

// Fixed problem shape: x[B=4, C=256, H=200, W=320] float32 -> out[B, H, W] float32
#define Bn 4
#define Cn 256
#define Hn 200
#define Wn 320
#define HWn (Hn * Wn)            // 64000
#define CHWn (Cn * HWn)          // 16384000
#define HW4 (HWn / 4)            // 16000 float4 groups per channel plane
#define NPIX (Bn * HWn)          // 256000 pixels
#define NGRP (Bn * HW4)          // 64000 float4 pixel groups
#define NBIN (Bn * Cn)           // 1024 (batch, channel) bins

#define CHUNKS 4
#define CPC   (Cn / CHUNKS)      // 64 channels per chunk

#define NEG_INF (-CUDART_INF_F)

// ---- scratch (device globals; no allocation) ----
__device__ float4   g_pmax[CHUNKS * NGRP];   // 4 MB  per-chunk partial max
__device__ int4     g_pmeta[CHUNKS * NGRP];  // 4 MB  per-chunk (arg | cnt<<16)
__device__ float    g_mx[NPIX];              // 1 MB  merged depth-wise max
__device__ unsigned g_amf[NPIX];             // 1 MB  am | tie<<8
__device__ unsigned g_hist[NBIN];
__device__ unsigned g_cursor[NBIN];
__device__ unsigned g_list[NPIX];            // 1 MB  packed p | am<<18 | tie<<26

// ---------------- K1: channel-chunk partial depth-wise argmax ----------------
__global__ void __launch_bounds__(256)
phaseA_kernel(const float* __restrict__ x) {
    const int t = blockIdx.x * 256 + threadIdx.x;   // exact cover
    const int chunk = t / NGRP;
    const int gg    = t - chunk * NGRP;
    const int b     = gg / HW4;
    const int pg    = gg - b * HW4;

    const float4* __restrict__ src =
        reinterpret_cast<const float4*>(x + (size_t)b * CHWn
                                          + (size_t)chunk * CPC * HWn) + pg;

    float mx[4]; int am[4]; int cn[4];
#pragma unroll
    for (int k = 0; k < 4; ++k) { mx[k] = NEG_INF; am[k] = 0; cn[k] = 0; }

#pragma unroll 2
    for (int c0 = 0; c0 < CPC; c0 += 8) {
        float4 v[8];
#pragma unroll
        for (int j = 0; j < 8; ++j)
            v[j] = __ldg(src + (size_t)(c0 + j) * HW4);
#pragma unroll
        for (int j = 0; j < 8; ++j) {
            const float vv[4] = {v[j].x, v[j].y, v[j].z, v[j].w};
#pragma unroll
            for (int k = 0; k < 4; ++k) {
                const bool gt = vv[k] > mx[k];
                const bool eq = vv[k] == mx[k];
                cn[k] = gt ? 1 : (cn[k] + (eq ? 1 : 0));
                am[k] = gt ? (c0 + j) : am[k];
                mx[k] = fmaxf(mx[k], vv[k]);
            }
        }
    }

    g_pmax[t] = make_float4(mx[0], mx[1], mx[2], mx[3]);
    int4 meta;
    meta.x = (chunk * CPC + am[0]) | (cn[0] << 16);
    meta.y = (chunk * CPC + am[1]) | (cn[1] << 16);
    meta.z = (chunk * CPC + am[2]) | (cn[2] << 16);
    meta.w = (chunk * CPC + am[3]) | (cn[3] << 16);
    g_pmeta[t] = meta;
}

// ---------------- K0: zero the histogram (fresh every launch) ----------------
__global__ void zero_hist_kernel() {
    g_hist[threadIdx.x] = 0;
}

// ---------------- K2: merge partials per pixel + histogram -------------------
__global__ void __launch_bounds__(256)
merge_count_kernel() {
    __shared__ unsigned s_cnt[NBIN];
#pragma unroll
    for (int i = 0; i < NBIN / 256; ++i)
        s_cnt[threadIdx.x + i * 256] = 0;
    __syncthreads();

    const int p = blockIdx.x * 256 + threadIdx.x;   // exact cover
    const float* __restrict__ pmax  = reinterpret_cast<const float*>(g_pmax);
    const int*   __restrict__ pmeta = reinterpret_cast<const int*>(g_pmeta);

    float mx = NEG_INF; int am = 0; int cn = 0;
#pragma unroll
    for (int ch = 0; ch < CHUNKS; ++ch) {
        const float m    = pmax[ch * NPIX + p];
        const int   meta = pmeta[ch * NPIX + p];
        const bool gt = m > mx;
        const bool eq = m == mx;
        cn = gt ? (meta >> 16) : (cn + (eq ? (meta >> 16) : 0));
        am = gt ? (meta & 0xFFFF) : am;
        mx = fmaxf(mx, m);
    }
    const unsigned tie = (cn > 1) ? 1u : 0u;
    g_mx[p]  = mx;
    g_amf[p] = (unsigned)am | (tie << 8);

    const int b = p / HWn;
    atomicAdd(&s_cnt[b * Cn + am], 1u);
    __syncthreads();
#pragma unroll
    for (int i = 0; i < NBIN / 256; ++i) {
        const unsigned c = s_cnt[threadIdx.x + i * 256];
        if (c) atomicAdd(&g_hist[threadIdx.x + i * 256], c);
    }
}

// ---------------- K3: exclusive scan of 1024 bins (one block) ----------------
__global__ void __launch_bounds__(NBIN)
scan_kernel() {
    __shared__ unsigned s[NBIN];
    const int i = threadIdx.x;
    s[i] = g_hist[i];
    __syncthreads();
    // Hillis-Steele inclusive scan
    for (int d = 1; d < NBIN; d <<= 1) {
        unsigned add = (i >= d) ? s[i - d] : 0u;
        __syncthreads();
        s[i] += add;
        __syncthreads();
    }
    const unsigned excl = s[i] - g_hist[i];
    g_cursor[i] = excl;
}

// ---------------- K4: scatter pixel ids into bin-sorted list -----------------
__global__ void __launch_bounds__(256)
scatter_kernel() {
    const int p = blockIdx.x * 256 + threadIdx.x;   // exact cover
    const unsigned amf = g_amf[p];
    const unsigned am  = amf & 0xFF;
    const unsigned tie = amf >> 8;
    const int b = p / HWn;
    const unsigned slot = atomicAdd(&g_cursor[b * Cn + am], 1u);
    g_list[slot] = (unsigned)p | (am << 18) | (tie << 26);
}

// Max over the 9x9 window (clipped) of one channel plane; fixed 9 rows
// (clamped duplicates harmless under max), 27 independent LDG.128.
__device__ __forceinline__ float window_max(const float* __restrict__ chan,
                                            int h, int w) {
    const int lo = w - 4;
    const int hi = w + 4;
    int wa = (w - 4) & ~3;
    if (wa < 0) wa = 0;
    if (wa > Wn - 12) wa = Wn - 12;   // 308, stays 16B-aligned

    float nb = NEG_INF;
#pragma unroll
    for (int i = 0; i < 9; ++i) {
        const int r = min(max(h - 4 + i, 0), Hn - 1);
        const float4* p = reinterpret_cast<const float4*>(chan + r * Wn + wa);
        float4 a = __ldg(p + 0);
        float4 b = __ldg(p + 1);
        float4 c = __ldg(p + 2);
        float v[12] = {a.x, a.y, a.z, a.w, b.x, b.y, b.z, b.w, c.x, c.y, c.z, c.w};
#pragma unroll
        for (int j = 0; j < 12; ++j) {
            const int col = wa + j;
            const bool ok = (col >= lo) && (col <= hi);
            nb = fmaxf(nb, ok ? v[j] : NEG_INF);
        }
    }
    return nb;
}

// ---------------- K5: bin-ordered 9x9 gather ---------------------------------
__global__ void __launch_bounds__(256)
gather_kernel(const float* __restrict__ x, float* __restrict__ out) {
    const int t = blockIdx.x * 256 + threadIdx.x;   // exact cover of NPIX
    const unsigned e = g_list[t];
    const int p   = (int)(e & 0x3FFFFu);
    const int am  = (int)((e >> 18) & 0xFFu);
    const int tie = (int)(e >> 26);

    const int b  = p / HWn;
    const int rm = p - b * HWn;
    const int h  = rm / Wn;
    const int w  = rm - h * Wn;

    const float mx = g_mx[p];
    const float* __restrict__ xb = x + (size_t)b * CHWn;

    float res;
    if (!tie) {
        const float nb = window_max(xb + (size_t)am * HWn, h, w);
        res = (nb <= mx) ? mx : 0.0f;   // nb >= mx always (center included)
    } else {
        // Exact tie path (statistically ~0 pixels).
        const float* xp = xb + h * Wn + w;
        int cnt = 0;
        for (int c = 0; c < Cn; ++c) {
            const float v = __ldg(xp + (size_t)c * HWn);
            if (v == mx) {
                if (window_max(xb + (size_t)c * HWn, h, w) <= mx) cnt++;
            }
        }
        res = mx * (float)cnt;
    }
    out[p] = res;
}

extern "C" void kernel_launch(void* const* d_in, const int* in_sizes, int n_in,
                              void* d_out, int out_size) {
    const float* x = (const float*)d_in[0];
    float* out = (float*)d_out;
    (void)in_sizes; (void)n_in; (void)out_size;

    phaseA_kernel<<<(CHUNKS * NGRP) / 256, 256>>>(x);   // 1000 blocks
    zero_hist_kernel<<<1, NBIN>>>();
    merge_count_kernel<<<NPIX / 256, 256>>>();          // 1000 blocks
    scan_kernel<<<1, NBIN>>>();
    scatter_kernel<<<NPIX / 256, 256>>>();              // 1000 blocks
    gather_kernel<<<NPIX / 256, 256>>>(x, out);         // 1000 blocks
}